// round 1
// baseline (speedup 1.0000x reference)
#include <cuda_runtime.h>
#include <cuda_bf16.h>
#include <math.h>

// Problem constants
#define PB  32
#define PM  10
#define PN  1000
#define MN  1010          // M + N
#define PD  128
#define NODES_TOTAL (PB*MN*PD)   // 4,136,960

// Scratch (device globals — no allocation allowed)
__device__ float g_peproj[PM*PD];     // alpha * (pe @ W_posproj.T)
__device__ float g_vpref[PD];         // Wp @ W_pref[:,0]
__device__ float g_Wnc[PD*5];         // Wn @ W_clients   (128x5)
__device__ float g_Wna[PD*4];         // Wn @ W_agents    (128x4)
__device__ float g_A[PB*PM*PD];       // depot_agents_embedding @ Wd.T

// ---------------------------------------------------------------------------
// Kernel 1: tiny weight precomputations. grid=13 blocks, 256 threads.
//   block 0      : g_vpref
//   block 1      : g_Wnc
//   block 2      : g_Wna
//   blocks 3..12 : g_peproj row i = blockIdx-3
// ---------------------------------------------------------------------------
__global__ void k_pre(const float* __restrict__ Wpp,    // W_posproj (128x128)
                      const float* __restrict__ alpha,  // (1,)
                      const float* __restrict__ Wfin,   // W_final (128x384)
                      const float* __restrict__ Wpref,  // W_pref (128x1)
                      const float* __restrict__ Wc,     // W_clients (128x5)
                      const float* __restrict__ Wa)     // W_agents (128x4)
{
    const int bid  = blockIdx.x;
    const int tid  = threadIdx.x;
    const int lane = tid & 31;
    const int warp = tid >> 5;   // 0..7

    if (bid == 0) {
        // v_pref[d1] = sum_e Wfin[d1,128+e] * Wpref[e]
        for (int d1 = warp * 16; d1 < warp * 16 + 16; d1++) {
            float s = 0.f;
            #pragma unroll
            for (int t = 0; t < 4; t++) {
                int e = lane + 32 * t;
                s += Wfin[d1 * 384 + 128 + e] * Wpref[e];
            }
            #pragma unroll
            for (int o = 16; o; o >>= 1) s += __shfl_xor_sync(0xffffffffu, s, o);
            if (lane == 0) g_vpref[d1] = s;
        }
    } else if (bid == 1) {
        // Wnc[d1,k] = sum_e Wfin[d1,e] * Wc[e,k]   (640 outputs)
        __shared__ float sWc[PD * 5];
        for (int i = tid; i < PD * 5; i += blockDim.x) sWc[i] = Wc[i];
        __syncthreads();
        for (int o = warp * 80; o < warp * 80 + 80; o++) {
            int d1 = o / 5, k = o % 5;
            float s = 0.f;
            #pragma unroll
            for (int t = 0; t < 4; t++) {
                int e = lane + 32 * t;
                s += Wfin[d1 * 384 + e] * sWc[e * 5 + k];
            }
            #pragma unroll
            for (int off = 16; off; off >>= 1) s += __shfl_xor_sync(0xffffffffu, s, off);
            if (lane == 0) g_Wnc[o] = s;
        }
    } else if (bid == 2) {
        // Wna[d1,k] = sum_e Wfin[d1,e] * Wa[e,k]   (512 outputs)
        __shared__ float sWa[PD * 4];
        for (int i = tid; i < PD * 4; i += blockDim.x) sWa[i] = Wa[i];
        __syncthreads();
        for (int o = warp * 64; o < warp * 64 + 64; o++) {
            int d1 = o / 4, k = o % 4;
            float s = 0.f;
            #pragma unroll
            for (int t = 0; t < 4; t++) {
                int e = lane + 32 * t;
                s += Wfin[d1 * 384 + e] * sWa[e * 4 + k];
            }
            #pragma unroll
            for (int off = 16; off; off >>= 1) s += __shfl_xor_sync(0xffffffffu, s, off);
            if (lane == 0) g_Wna[o] = s;
        }
    } else {
        // Positional-encoding projection for row i.
        const int i = bid - 3;    // 0..9
        __shared__ float spe[PD];
        if (tid < PD) {
            int k = tid >> 1;
            float dv  = expf((float)(2 * k) * (-logf(10000.0f) / (float)PD));
            float ang = (float)i * dv;
            spe[tid] = (tid & 1) ? cosf(ang) : sinf(ang);
        }
        __syncthreads();
        float a = alpha[0];
        for (int d1 = warp * 16; d1 < warp * 16 + 16; d1++) {
            float s = 0.f;
            #pragma unroll
            for (int t = 0; t < 4; t++) {
                int e = lane + 32 * t;
                s += spe[e] * Wpp[d1 * PD + e];
            }
            #pragma unroll
            for (int off = 16; off; off >>= 1) s += __shfl_xor_sync(0xffffffffu, s, off);
            if (lane == 0) g_peproj[i * PD + d1] = a * s;
        }
    }
}

// ---------------------------------------------------------------------------
// Kernel 2: per-agent A = (concat(depot_emb, agents_emb) @ Wda.T) @ Wd.T
// grid = B*M = 320 blocks, 128 threads (4 warps).
// ---------------------------------------------------------------------------
__global__ void k_agents(const float* __restrict__ locs,   // (B,1010,2)
                         const float* __restrict__ cap,    // (B,10)
                         const float* __restrict__ spd,    // (B,10)
                         const float* __restrict__ Wdep,   // W_depot (128x2)
                         const float* __restrict__ Wa,     // W_agents (128x4)
                         const float* __restrict__ Wda,    // W_depot_agents (128x256)
                         const float* __restrict__ Wfin)   // W_final (128x384)
{
    const int b = blockIdx.x / PM;
    const int i = blockIdx.x % PM;
    const int d = threadIdx.x;           // 0..127
    const int lane = d & 31;
    const int warp = d >> 5;             // 0..3

    __shared__ float sde[PD], sae[PD], sdA[PD];

    const float lx = locs[(b * MN + i) * 2 + 0];
    const float ly = locs[(b * MN + i) * 2 + 1];
    const float c  = cap[b * PM + i] * (1.0f / 40.0f);
    const float sp = spd[b * PM + i];

    // agents_embedding[d] and depot_embedding[d]
    sae[d] = lx * Wa[d * 4 + 0] + ly * Wa[d * 4 + 1] + c * Wa[d * 4 + 2] + sp * Wa[d * 4 + 3];
    sde[d] = lx * Wdep[d * 2 + 0] + ly * Wdep[d * 2 + 1] + g_peproj[i * PD + d];
    __syncthreads();

    // depA[d1] = sum_c sde[c]*Wda[d1,c] + sum_c sae[c]*Wda[d1,128+c]
    for (int r = 0; r < 32; r++) {
        int d1 = warp * 32 + r;
        float s = 0.f;
        #pragma unroll
        for (int t = 0; t < 4; t++) {
            int e = lane + 32 * t;
            s += sde[e] * Wda[d1 * 256 + e] + sae[e] * Wda[d1 * 256 + 128 + e];
        }
        #pragma unroll
        for (int off = 16; off; off >>= 1) s += __shfl_xor_sync(0xffffffffu, s, off);
        if (lane == 0) sdA[d1] = s;
    }
    __syncthreads();

    // A[d1] = sum_e depA[e] * Wfin[d1, 256+e]
    for (int r = 0; r < 32; r++) {
        int d1 = warp * 32 + r;
        float s = 0.f;
        #pragma unroll
        for (int t = 0; t < 4; t++) {
            int e = lane + 32 * t;
            s += sdA[e] * Wfin[d1 * 384 + 256 + e];
        }
        #pragma unroll
        for (int off = 16; off; off >>= 1) s += __shfl_xor_sync(0xffffffffu, s, off);
        if (lane == 0) g_A[(b * PM + i) * PD + d1] = s;
    }
}

// ---------------------------------------------------------------------------
// Kernel 3: main streaming kernel. One block per (b, j) node.
// Emits nodes_embedding row + 10 combined_embedding rows.
// grid = B*MN = 32320 blocks, 128 threads.
// ---------------------------------------------------------------------------
__global__ void k_main(const float* __restrict__ locs,    // (B,1010,2)
                       const float* __restrict__ cap,     // (B,10)
                       const float* __restrict__ spd,     // (B,10)
                       const float* __restrict__ demand,  // (B,1,1010)
                       const float* __restrict__ pref,    // (B,10,1010)
                       const float* __restrict__ Wa,      // W_agents (128x4)
                       const float* __restrict__ Wc,      // W_clients (128x5)
                       float* __restrict__ out)
{
    const int bj = blockIdx.x;
    const int b  = bj / MN;
    const int j  = bj % MN;
    const int d  = threadIdx.x;

    float ne, nw;
    const float lx = locs[(b * MN + j) * 2 + 0];
    const float ly = locs[(b * MN + j) * 2 + 1];

    if (j < PM) {
        // agent node: feats = [x, y, cap/40, speed]
        const float c  = cap[b * PM + j] * (1.0f / 40.0f);
        const float sp = spd[b * PM + j];
        ne = lx * Wa[d * 4 + 0] + ly * Wa[d * 4 + 1] + c * Wa[d * 4 + 2] + sp * Wa[d * 4 + 3];
        nw = lx * g_Wna[d * 4 + 0] + ly * g_Wna[d * 4 + 1] + c * g_Wna[d * 4 + 2] + sp * g_Wna[d * 4 + 3];
    } else {
        // client node: feats = [x, y, dem/40, dist, angle]
        const float dx   = lx - locs[b * MN * 2 + 0];
        const float dy   = ly - locs[b * MN * 2 + 1];
        const float dist = sqrtf(dx * dx + dy * dy);
        const float ang  = atan2f(dy, dx);
        const float dem  = demand[b * MN + j] * (1.0f / 40.0f);
        ne = lx * Wc[d * 5 + 0] + ly * Wc[d * 5 + 1] + dem * Wc[d * 5 + 2]
           + dist * Wc[d * 5 + 3] + ang * Wc[d * 5 + 4];
        nw = lx * g_Wnc[d * 5 + 0] + ly * g_Wnc[d * 5 + 1] + dem * g_Wnc[d * 5 + 2]
           + dist * g_Wnc[d * 5 + 3] + ang * g_Wnc[d * 5 + 4];
    }

    // nodes_embedding output
    out[(b * MN + j) * PD + d] = ne;

    const float vp = g_vpref[d];
    float* __restrict__ out2 = out + NODES_TOTAL;

    #pragma unroll
    for (int i = 0; i < PM; i++) {
        const float p = __ldg(&pref[(b * PM + i) * MN + j]);     // broadcast scalar
        const float a = g_A[(b * PM + i) * PD + d];              // L2-resident
        out2[((b * PM + i) * MN + j) * PD + d] = nw + p * vp + a;
    }
}

// ---------------------------------------------------------------------------
extern "C" void kernel_launch(void* const* d_in, const int* in_sizes, int n_in,
                              void* d_out, int out_size)
{
    const float* locs      = (const float*)d_in[0];
    const float* capacity  = (const float*)d_in[1];
    const float* speed     = (const float*)d_in[2];
    const float* demand    = (const float*)d_in[3];
    const float* pref      = (const float*)d_in[4];
    // d_in[5] = action_mask (bool) — only its shape matters, unused
    const float* W_depot   = (const float*)d_in[6];
    const float* W_posproj = (const float*)d_in[7];
    const float* alpha     = (const float*)d_in[8];
    const float* W_agents  = (const float*)d_in[9];
    const float* W_da      = (const float*)d_in[10];
    const float* W_clients = (const float*)d_in[11];
    const float* W_pref    = (const float*)d_in[12];
    const float* W_final   = (const float*)d_in[13];
    float* out = (float*)d_out;

    k_pre<<<13, 256>>>(W_posproj, alpha, W_final, W_pref, W_clients, W_agents);
    k_agents<<<PB * PM, PD>>>(locs, capacity, speed, W_depot, W_agents, W_da, W_final);
    k_main<<<PB * MN, PD>>>(locs, capacity, speed, demand, pref, W_agents, W_clients, out);
}

// round 2
// speedup vs baseline: 2.3516x; 2.3516x over previous
#include <cuda_runtime.h>
#include <cuda_bf16.h>
#include <math.h>

// Problem constants
#define PB  32
#define PM  10
#define PN  1000
#define MN  1010          // M + N
#define PD  128
#define NODES_TOTAL (PB*MN*PD)   // 4,136,960

// Scratch (device globals — no allocation allowed)
__device__ float g_peproj[PM*PD];     // alpha * (pe @ W_posproj.T)
__device__ float g_vpref[PD];         // Wp @ W_pref[:,0]
__device__ float g_Wnc[PD*5];         // Wn @ W_clients   (128x5)
__device__ float g_Wna[PD*4];         // Wn @ W_agents    (128x4)
__device__ float g_A[PB*PM*PD];       // final agent-broadcast term (B*M x 128)

// ---------------------------------------------------------------------------
// Kernel 1: weight precomputations, one WARP per dot-128 output.
// Tasks: [0,128)        -> g_vpref
//        [128,768)      -> g_Wnc   (o = t-128;  d1=o/5, k=o%5)
//        [768,1280)     -> g_Wna   (o = t-768;  d1=o/4, k=o%4)
//        [1280,2560)    -> g_peproj (o = t-1280; i=o/128, d1=o%128)
// grid = 320 blocks x 256 threads (8 warps) = 2560 warps.
// ---------------------------------------------------------------------------
__global__ void k_pre(const float* __restrict__ Wpp,    // W_posproj (128x128)
                      const float* __restrict__ alpha,  // (1,)
                      const float* __restrict__ Wfin,   // W_final (128x384)
                      const float* __restrict__ Wpref,  // W_pref (128x1)
                      const float* __restrict__ Wc,     // W_clients (128x5)
                      const float* __restrict__ Wa)     // W_agents (128x4)
{
    const int lane = threadIdx.x & 31;
    const int t    = blockIdx.x * 8 + (threadIdx.x >> 5);   // global warp id

    float s = 0.f;

    if (t < 128) {
        const int d1 = t;
        #pragma unroll
        for (int q = 0; q < 4; q++) {
            int e = lane + 32 * q;
            s += Wfin[d1 * 384 + 128 + e] * Wpref[e];
        }
        #pragma unroll
        for (int o = 16; o; o >>= 1) s += __shfl_xor_sync(0xffffffffu, s, o);
        if (lane == 0) g_vpref[d1] = s;
    } else if (t < 768) {
        const int o = t - 128, d1 = o / 5, k = o % 5;
        #pragma unroll
        for (int q = 0; q < 4; q++) {
            int e = lane + 32 * q;
            s += Wfin[d1 * 384 + e] * __ldg(&Wc[e * 5 + k]);
        }
        #pragma unroll
        for (int off = 16; off; off >>= 1) s += __shfl_xor_sync(0xffffffffu, s, off);
        if (lane == 0) g_Wnc[o] = s;
    } else if (t < 1280) {
        const int o = t - 768, d1 = o / 4, k = o % 4;
        #pragma unroll
        for (int q = 0; q < 4; q++) {
            int e = lane + 32 * q;
            s += Wfin[d1 * 384 + e] * __ldg(&Wa[e * 4 + k]);
        }
        #pragma unroll
        for (int off = 16; off; off >>= 1) s += __shfl_xor_sync(0xffffffffu, s, off);
        if (lane == 0) g_Wna[o] = s;
    } else {
        const int o = t - 1280, i = o / PD, d1 = o % PD;
        const float nl = -logf(10000.0f) / (float)PD;
        #pragma unroll
        for (int q = 0; q < 4; q++) {
            int e = lane + 32 * q;
            int k2 = (e >> 1) * 2;                 // 2*(e/2)
            float dv  = expf((float)k2 * nl);
            float ang = (float)i * dv;
            float pe  = (e & 1) ? cosf(ang) : sinf(ang);
            s += pe * Wpp[d1 * PD + e];
        }
        #pragma unroll
        for (int off = 16; off; off >>= 1) s += __shfl_xor_sync(0xffffffffu, s, off);
        if (lane == 0) g_peproj[i * PD + d1] = alpha[0] * s;
    }
}

// ---------------------------------------------------------------------------
// Kernel 2: per-agent A = ((concat(depot_emb, agents_emb) @ Wda.T) @ Wd.T)
// grid = B*M = 320 blocks, 128 threads (4 warps).
// ---------------------------------------------------------------------------
__global__ void k_agents(const float* __restrict__ locs,   // (B,1010,2)
                         const float* __restrict__ cap,    // (B,10)
                         const float* __restrict__ spd,    // (B,10)
                         const float* __restrict__ Wdep,   // W_depot (128x2)
                         const float* __restrict__ Wa,     // W_agents (128x4)
                         const float* __restrict__ Wda,    // W_depot_agents (128x256)
                         const float* __restrict__ Wfin)   // W_final (128x384)
{
    const int b = blockIdx.x / PM;
    const int i = blockIdx.x % PM;
    const int d = threadIdx.x;           // 0..127
    const int lane = d & 31;
    const int warp = d >> 5;             // 0..3

    __shared__ float sde[PD], sae[PD], sdA[PD];

    const float lx = locs[(b * MN + i) * 2 + 0];
    const float ly = locs[(b * MN + i) * 2 + 1];
    const float c  = cap[b * PM + i] * (1.0f / 40.0f);
    const float sp = spd[b * PM + i];

    sae[d] = lx * Wa[d * 4 + 0] + ly * Wa[d * 4 + 1] + c * Wa[d * 4 + 2] + sp * Wa[d * 4 + 3];
    sde[d] = lx * Wdep[d * 2 + 0] + ly * Wdep[d * 2 + 1] + g_peproj[i * PD + d];
    __syncthreads();

    for (int r = 0; r < 32; r++) {
        int d1 = warp * 32 + r;
        float s = 0.f;
        #pragma unroll
        for (int q = 0; q < 4; q++) {
            int e = lane + 32 * q;
            s += sde[e] * Wda[d1 * 256 + e] + sae[e] * Wda[d1 * 256 + 128 + e];
        }
        #pragma unroll
        for (int off = 16; off; off >>= 1) s += __shfl_xor_sync(0xffffffffu, s, off);
        if (lane == 0) sdA[d1] = s;
    }
    __syncthreads();

    for (int r = 0; r < 32; r++) {
        int d1 = warp * 32 + r;
        float s = 0.f;
        #pragma unroll
        for (int q = 0; q < 4; q++) {
            int e = lane + 32 * q;
            s += sdA[e] * Wfin[d1 * 384 + 256 + e];
        }
        #pragma unroll
        for (int off = 16; off; off >>= 1) s += __shfl_xor_sync(0xffffffffu, s, off);
        if (lane == 0) g_A[(b * PM + i) * PD + d1] = s;
    }
}

// ---------------------------------------------------------------------------
// Kernel 3: main streaming kernel. One WARP per (b, j); each lane owns 4
// consecutive d-values (float4). Emits nodes row + 10 combined rows as
// STG.128 streaming stores.
// grid = B*MN/8 = 4040 blocks, 256 threads (8 warps).
// ---------------------------------------------------------------------------
__global__ void __launch_bounds__(256) k_main(
                       const float* __restrict__ locs,    // (B,1010,2)
                       const float* __restrict__ cap,     // (B,10)
                       const float* __restrict__ spd,     // (B,10)
                       const float* __restrict__ demand,  // (B,1,1010)
                       const float* __restrict__ pref,    // (B,10,1010)
                       const float* __restrict__ Wa,      // W_agents (128x4)
                       const float* __restrict__ Wc,      // W_clients (128x5)
                       float* __restrict__ out)
{
    const int lane = threadIdx.x & 31;
    const int jg   = blockIdx.x * 8 + (threadIdx.x >> 5);  // global (b,j) index
    const int b    = jg / MN;
    const int j    = jg - b * MN;
    const int d0   = lane * 4;

    const float lx = locs[(b * MN + j) * 2 + 0];
    const float ly = locs[(b * MN + j) * 2 + 1];

    float nev[4], nwv[4];

    if (j < PM) {
        const float c  = cap[b * PM + j] * (1.0f / 40.0f);
        const float sp = spd[b * PM + j];
        #pragma unroll
        for (int r = 0; r < 4; r++) {
            const int d = d0 + r;
            nev[r] = lx * __ldg(&Wa[d * 4 + 0]) + ly * __ldg(&Wa[d * 4 + 1])
                   + c  * __ldg(&Wa[d * 4 + 2]) + sp * __ldg(&Wa[d * 4 + 3]);
            nwv[r] = lx * g_Wna[d * 4 + 0] + ly * g_Wna[d * 4 + 1]
                   + c  * g_Wna[d * 4 + 2] + sp * g_Wna[d * 4 + 3];
        }
    } else {
        const float dx   = lx - __ldg(&locs[b * MN * 2 + 0]);
        const float dy   = ly - __ldg(&locs[b * MN * 2 + 1]);
        const float dist = sqrtf(dx * dx + dy * dy);
        const float ang  = atan2f(dy, dx);
        const float dem  = __ldg(&demand[b * MN + j]) * (1.0f / 40.0f);
        #pragma unroll
        for (int r = 0; r < 4; r++) {
            const int d = d0 + r;
            nev[r] = lx   * __ldg(&Wc[d * 5 + 0]) + ly  * __ldg(&Wc[d * 5 + 1])
                   + dem  * __ldg(&Wc[d * 5 + 2]) + dist * __ldg(&Wc[d * 5 + 3])
                   + ang  * __ldg(&Wc[d * 5 + 4]);
            nwv[r] = lx   * g_Wnc[d * 5 + 0] + ly   * g_Wnc[d * 5 + 1]
                   + dem  * g_Wnc[d * 5 + 2] + dist * g_Wnc[d * 5 + 3]
                   + ang  * g_Wnc[d * 5 + 4];
        }
    }

    // nodes_embedding row (streaming store: write-only region)
    float4 nef = make_float4(nev[0], nev[1], nev[2], nev[3]);
    __stcs(reinterpret_cast<float4*>(&out[(b * MN + j) * PD + d0]), nef);

    const float4 vp = *reinterpret_cast<const float4*>(&g_vpref[d0]);
    float* __restrict__ out2 = out + NODES_TOTAL;

    #pragma unroll
    for (int i = 0; i < PM; i++) {
        const float  p = __ldg(&pref[(b * PM + i) * MN + j]);
        const float4 a = *reinterpret_cast<const float4*>(&g_A[(b * PM + i) * PD + d0]);
        float4 v;
        v.x = nwv[0] + p * vp.x + a.x;
        v.y = nwv[1] + p * vp.y + a.y;
        v.z = nwv[2] + p * vp.z + a.z;
        v.w = nwv[3] + p * vp.w + a.w;
        __stcs(reinterpret_cast<float4*>(&out2[((b * PM + i) * MN + j) * PD + d0]), v);
    }
}

// ---------------------------------------------------------------------------
extern "C" void kernel_launch(void* const* d_in, const int* in_sizes, int n_in,
                              void* d_out, int out_size)
{
    const float* locs      = (const float*)d_in[0];
    const float* capacity  = (const float*)d_in[1];
    const float* speed     = (const float*)d_in[2];
    const float* demand    = (const float*)d_in[3];
    const float* pref      = (const float*)d_in[4];
    // d_in[5] = action_mask (bool) — unused
    const float* W_depot   = (const float*)d_in[6];
    const float* W_posproj = (const float*)d_in[7];
    const float* alpha     = (const float*)d_in[8];
    const float* W_agents  = (const float*)d_in[9];
    const float* W_da      = (const float*)d_in[10];
    const float* W_clients = (const float*)d_in[11];
    const float* W_pref    = (const float*)d_in[12];
    const float* W_final   = (const float*)d_in[13];
    float* out = (float*)d_out;

    k_pre<<<320, 256>>>(W_posproj, alpha, W_final, W_pref, W_clients, W_agents);
    k_agents<<<PB * PM, PD>>>(locs, capacity, speed, W_depot, W_agents, W_da, W_final);
    k_main<<<(PB * MN) / 8, 256>>>(locs, capacity, speed, demand, pref,
                                   W_agents, W_clients, out);
}

// round 3
// speedup vs baseline: 2.8994x; 1.2329x over previous
#include <cuda_runtime.h>
#include <cuda_bf16.h>
#include <math.h>

// Problem constants
#define PB  32
#define PM  10
#define PN  1000
#define MN  1010          // M + N
#define PD  128
#define NODES_TOTAL (PB*MN*PD)   // 4,136,960
#define JT  8              // j-nodes per block in k_main
#define NTILE ((MN + JT - 1) / JT)   // 127

// Scratch (device globals — no allocation allowed)
__device__ __align__(16) float g_vpref[PD];      // Wp @ W_pref[:,0]
__device__ __align__(16) float g_Wnc[PD*5];      // Wn @ W_clients (128x5)
__device__ __align__(16) float g_Wna[PD*4];      // Wn @ W_agents  (128x4)
__device__ __align__(16) float g_A[PB*PM*PD];    // agent broadcast term (B*M x 128)

// ---------------------------------------------------------------------------
// Fused prologue kernel. 480 blocks x 256 threads.
//  blocks [0,160): weight folds, one warp per dot-128 output (1280 warps):
//     warp t in [0,128)    -> g_vpref
//     t in [128,768)       -> g_Wnc  (o=t-128; d1=o/5, k=o%5)
//     t in [768,1280)      -> g_Wna  (o=t-768; d1=o/4, k=o%4)
//  blocks [160,480): per-(b,i) agent pipeline -> g_A. Computes its own
//     positional-encoding projection (no cross-block dependency).
// ---------------------------------------------------------------------------
__global__ void __launch_bounds__(256) k_pro(
                      const float* __restrict__ Wpp,    // W_posproj (128x128)
                      const float* __restrict__ alpha,  // (1,)
                      const float* __restrict__ Wfin,   // W_final (128x384)
                      const float* __restrict__ Wpref,  // W_pref (128x1)
                      const float* __restrict__ Wc,     // W_clients (128x5)
                      const float* __restrict__ Wa,     // W_agents (128x4)
                      const float* __restrict__ locs,   // (B,1010,2)
                      const float* __restrict__ cap,    // (B,10)
                      const float* __restrict__ spd,    // (B,10)
                      const float* __restrict__ Wdep,   // W_depot (128x2)
                      const float* __restrict__ Wda)    // W_depot_agents (128x256)
{
    const int lane = threadIdx.x & 31;
    const int warp = threadIdx.x >> 5;    // 0..7

    if (blockIdx.x < 160) {
        // ------- weight folds -------
        const int t = blockIdx.x * 8 + warp;
        float s = 0.f;
        if (t < 128) {
            const int d1 = t;
            #pragma unroll
            for (int q = 0; q < 4; q++) {
                int e = lane + 32 * q;
                s += Wfin[d1 * 384 + 128 + e] * Wpref[e];
            }
            #pragma unroll
            for (int o = 16; o; o >>= 1) s += __shfl_xor_sync(0xffffffffu, s, o);
            if (lane == 0) g_vpref[d1] = s;
        } else if (t < 768) {
            const int o = t - 128, d1 = o / 5, k = o % 5;
            #pragma unroll
            for (int q = 0; q < 4; q++) {
                int e = lane + 32 * q;
                s += Wfin[d1 * 384 + e] * __ldg(&Wc[e * 5 + k]);
            }
            #pragma unroll
            for (int off = 16; off; off >>= 1) s += __shfl_xor_sync(0xffffffffu, s, off);
            if (lane == 0) g_Wnc[o] = s;
        } else {
            const int o = t - 768, d1 = o / 4, k = o % 4;
            #pragma unroll
            for (int q = 0; q < 4; q++) {
                int e = lane + 32 * q;
                s += Wfin[d1 * 384 + e] * __ldg(&Wa[e * 4 + k]);
            }
            #pragma unroll
            for (int off = 16; off; off >>= 1) s += __shfl_xor_sync(0xffffffffu, s, off);
            if (lane == 0) g_Wna[o] = s;
        }
        return;
    }

    // ------- agent pipeline: one block per (b, i) -------
    const int idx = blockIdx.x - 160;     // 0..319
    const int b = idx / PM;
    const int i = idx % PM;
    const int tid = threadIdx.x;

    __shared__ float spe[PD], sde[PD], sae[PD], sdA[PD];

    const float lx = __ldg(&locs[(b * MN + i) * 2 + 0]);
    const float ly = __ldg(&locs[(b * MN + i) * 2 + 1]);
    const float c  = __ldg(&cap[b * PM + i]) * (1.0f / 40.0f);
    const float sp = __ldg(&spd[b * PM + i]);

    if (tid < PD) {
        // agents_embedding[d]
        sae[tid] = lx * Wa[tid * 4 + 0] + ly * Wa[tid * 4 + 1]
                 + c  * Wa[tid * 4 + 2] + sp * Wa[tid * 4 + 3];
        // positional encoding value for index tid
        const float nl = -logf(10000.0f) / (float)PD;
        int k2 = (tid >> 1) * 2;
        float ang = (float)i * expf((float)k2 * nl);
        spe[tid] = (tid & 1) ? cosf(ang) : sinf(ang);
    }
    __syncthreads();

    // depot_embedding: sde[d1] = lx*Wdep + ly*Wdep + alpha * sum_e spe[e]*Wpp[d1,e]
    const float a0 = __ldg(&alpha[0]);
    for (int r = 0; r < 16; r++) {
        int d1 = warp * 16 + r;
        float s = 0.f;
        #pragma unroll
        for (int q = 0; q < 4; q++) {
            int e = lane + 32 * q;
            s += spe[e] * Wpp[d1 * PD + e];
        }
        #pragma unroll
        for (int off = 16; off; off >>= 1) s += __shfl_xor_sync(0xffffffffu, s, off);
        if (lane == 0)
            sde[d1] = lx * Wdep[d1 * 2 + 0] + ly * Wdep[d1 * 2 + 1] + a0 * s;
    }
    __syncthreads();

    // depA[d1] = sum_e sde[e]*Wda[d1,e] + sae[e]*Wda[d1,128+e]
    for (int r = 0; r < 16; r++) {
        int d1 = warp * 16 + r;
        float s = 0.f;
        #pragma unroll
        for (int q = 0; q < 4; q++) {
            int e = lane + 32 * q;
            s += sde[e] * Wda[d1 * 256 + e] + sae[e] * Wda[d1 * 256 + 128 + e];
        }
        #pragma unroll
        for (int off = 16; off; off >>= 1) s += __shfl_xor_sync(0xffffffffu, s, off);
        if (lane == 0) sdA[d1] = s;
    }
    __syncthreads();

    // A[d1] = sum_e sdA[e] * Wfin[d1, 256+e]
    for (int r = 0; r < 16; r++) {
        int d1 = warp * 16 + r;
        float s = 0.f;
        #pragma unroll
        for (int q = 0; q < 4; q++) {
            int e = lane + 32 * q;
            s += sdA[e] * Wfin[d1 * 384 + 256 + e];
        }
        #pragma unroll
        for (int off = 16; off; off >>= 1) s += __shfl_xor_sync(0xffffffffu, s, off);
        if (lane == 0) g_A[(b * PM + i) * PD + d1] = s;
    }
}

// ---------------------------------------------------------------------------
// Main streaming kernel. Grid = (NTILE, PB); block = 256 (8 warps).
// Block (tile, b): stages g_A[b] (5 KB) + v_pref into smem, then each warp
// handles node j = tile*8 + warp: 1 nodes row + 10 combined rows, all as
// STG.128 streaming stores. No global loads inside the store loop.
// ---------------------------------------------------------------------------
__global__ void __launch_bounds__(256) k_main(
                       const float* __restrict__ locs,    // (B,1010,2)
                       const float* __restrict__ cap,     // (B,10)
                       const float* __restrict__ spd,     // (B,10)
                       const float* __restrict__ demand,  // (B,1,1010)
                       const float* __restrict__ pref,    // (B,10,1010)
                       const float* __restrict__ Wa,      // W_agents (128x4)
                       const float* __restrict__ Wc,      // W_clients (128x5)
                       float* __restrict__ out)
{
    const int b    = blockIdx.y;
    const int tile = blockIdx.x;
    const int lane = threadIdx.x & 31;
    const int warp = threadIdx.x >> 5;

    __shared__ __align__(16) float sA[PM * PD];   // g_A rows for this b
    __shared__ __align__(16) float svp[PD];       // v_pref

    // Cooperative stage: 1280 + 128 floats via float4 (88 x float4 per 256 thr)
    {
        const float4* srcA = reinterpret_cast<const float4*>(&g_A[b * PM * PD]);
        float4* dstA = reinterpret_cast<float4*>(sA);
        for (int t = threadIdx.x; t < PM * PD / 4; t += 256) dstA[t] = srcA[t];
        if (threadIdx.x < PD / 4)
            reinterpret_cast<float4*>(svp)[threadIdx.x] =
                reinterpret_cast<const float4*>(g_vpref)[threadIdx.x];
    }
    __syncthreads();

    const int j = tile * JT + warp;
    if (j >= MN) return;

    const int d0 = lane * 4;
    const float lx = __ldg(&locs[(b * MN + j) * 2 + 0]);
    const float ly = __ldg(&locs[(b * MN + j) * 2 + 1]);

    float nev[4], nwv[4];

    if (j < PM) {
        const float c  = __ldg(&cap[b * PM + j]) * (1.0f / 40.0f);
        const float sp = __ldg(&spd[b * PM + j]);
        #pragma unroll
        for (int r = 0; r < 4; r++) {
            const int d = d0 + r;
            nev[r] = lx * __ldg(&Wa[d * 4 + 0]) + ly * __ldg(&Wa[d * 4 + 1])
                   + c  * __ldg(&Wa[d * 4 + 2]) + sp * __ldg(&Wa[d * 4 + 3]);
            nwv[r] = lx * g_Wna[d * 4 + 0] + ly * g_Wna[d * 4 + 1]
                   + c  * g_Wna[d * 4 + 2] + sp * g_Wna[d * 4 + 3];
        }
    } else {
        const float dx   = lx - __ldg(&locs[b * MN * 2 + 0]);
        const float dy   = ly - __ldg(&locs[b * MN * 2 + 1]);
        const float dist = sqrtf(dx * dx + dy * dy);
        const float ang  = atan2f(dy, dx);
        const float dem  = __ldg(&demand[b * MN + j]) * (1.0f / 40.0f);
        #pragma unroll
        for (int r = 0; r < 4; r++) {
            const int d = d0 + r;
            nev[r] = lx  * __ldg(&Wc[d * 5 + 0]) + ly   * __ldg(&Wc[d * 5 + 1])
                   + dem * __ldg(&Wc[d * 5 + 2]) + dist * __ldg(&Wc[d * 5 + 3])
                   + ang * __ldg(&Wc[d * 5 + 4]);
            nwv[r] = lx  * g_Wnc[d * 5 + 0] + ly   * g_Wnc[d * 5 + 1]
                   + dem * g_Wnc[d * 5 + 2] + dist * g_Wnc[d * 5 + 3]
                   + ang * g_Wnc[d * 5 + 4];
        }
    }

    // nodes_embedding row
    __stcs(reinterpret_cast<float4*>(&out[(b * MN + j) * PD + d0]),
           make_float4(nev[0], nev[1], nev[2], nev[3]));

    const float4 vp = *reinterpret_cast<const float4*>(&svp[d0]);
    float* __restrict__ out2 = out + NODES_TOTAL;

    // Prefetch all 10 pref scalars up front (independent loads, broadcast)
    float p[PM];
    #pragma unroll
    for (int i = 0; i < PM; i++)
        p[i] = __ldg(&pref[(b * PM + i) * MN + j]);

    #pragma unroll
    for (int i = 0; i < PM; i++) {
        const float4 a = *reinterpret_cast<const float4*>(&sA[i * PD + d0]);
        float4 v;
        v.x = nwv[0] + p[i] * vp.x + a.x;
        v.y = nwv[1] + p[i] * vp.y + a.y;
        v.z = nwv[2] + p[i] * vp.z + a.z;
        v.w = nwv[3] + p[i] * vp.w + a.w;
        __stcs(reinterpret_cast<float4*>(&out2[((b * PM + i) * MN + j) * PD + d0]), v);
    }
}

// ---------------------------------------------------------------------------
extern "C" void kernel_launch(void* const* d_in, const int* in_sizes, int n_in,
                              void* d_out, int out_size)
{
    const float* locs      = (const float*)d_in[0];
    const float* capacity  = (const float*)d_in[1];
    const float* speed     = (const float*)d_in[2];
    const float* demand    = (const float*)d_in[3];
    const float* pref      = (const float*)d_in[4];
    // d_in[5] = action_mask (bool) — unused
    const float* W_depot   = (const float*)d_in[6];
    const float* W_posproj = (const float*)d_in[7];
    const float* alpha     = (const float*)d_in[8];
    const float* W_agents  = (const float*)d_in[9];
    const float* W_da      = (const float*)d_in[10];
    const float* W_clients = (const float*)d_in[11];
    const float* W_pref    = (const float*)d_in[12];
    const float* W_final   = (const float*)d_in[13];
    float* out = (float*)d_out;

    k_pro<<<480, 256>>>(W_posproj, alpha, W_final, W_pref, W_clients, W_agents,
                        locs, capacity, speed, W_depot, W_da);

    dim3 grid(NTILE, PB);
    k_main<<<grid, 256>>>(locs, capacity, speed, demand, pref,
                          W_agents, W_clients, out);
}